// round 2
// baseline (speedup 1.0000x reference)
#include <cuda_runtime.h>
#include <math.h>

// SoftEquivariantLayer fused kernel, fp32, packed f32x2 FMA for the mixing GEMM.
// B=524288 rows of 128 floats (NB=8 bundles x BD=16).
// out[b, i, k] = z*(1+softplus(MLP(norms(z)))[i]) + sigmoid(gate_bias[i]) * mixing[b,i,k]
// mixing[b,ik] = sum_jd z[b,jd] * Wf[ik][jd],  Wf[ik][jd] = mix_w[i][j][k][d]

#define ROWS      128
#define THREADS   256
#define KDIM      128          // jd
#define ZS_STRIDE 132          // padded row stride (floats)
#define WT_STRIDE 132

// shared layout (floats)
#define OFF_ZS     0                         // [128][132]
#define OFF_WT     (OFF_ZS + ROWS*ZS_STRIDE) // [128][132]  Wt[jd][ik]
#define OFF_W2     (OFF_WT + KDIM*WT_STRIDE) // [64][64]
#define OFF_W1     (OFF_W2 + 64*64)          // [64][8]
#define OFF_W3     (OFF_W1 + 64*8)           // [8][64]
#define OFF_B1     (OFF_W3 + 8*64)           // [64]
#define OFF_B2     (OFF_B1 + 64)             // [64]
#define OFF_G      (OFF_B2 + 64)             // [8]
#define OFF_SC     (OFF_G + 8)               // [128][8]
#define SMEM_FLOATS (OFF_SC + ROWS*8)
#define SMEM_BYTES  (SMEM_FLOATS * 4)

__device__ __forceinline__ unsigned long long pack2(float lo, float hi) {
    unsigned long long r;
    asm("mov.b64 %0, {%1,%2};" : "=l"(r) : "f"(lo), "f"(hi));
    return r;
}
__device__ __forceinline__ void fma2(unsigned long long& d, unsigned long long a, unsigned long long b) {
    asm("fma.rn.f32x2 %0, %1, %2, %0;" : "+l"(d) : "l"(a), "l"(b));
}
__device__ __forceinline__ float2 unpack2(unsigned long long v) {
    float2 f;
    asm("mov.b64 {%0,%1}, %2;" : "=f"(f.x), "=f"(f.y) : "l"(v));
    return f;
}
__device__ __forceinline__ float gelu_exact(float x) {
    return 0.5f * x * (1.0f + erff(x * 0.7071067811865476f));
}
__device__ __forceinline__ float softplus_f(float x) {
    // numerically stable log(1+exp(x))
    if (x > 0.0f) return x + log1pf(expf(-x));
    return log1pf(expf(x));
}

__global__ void __launch_bounds__(THREADS, 1)
soft_equivariant_kernel(const float* __restrict__ z,
                        const float* __restrict__ w1,
                        const float* __restrict__ b1,
                        const float* __restrict__ w2,
                        const float* __restrict__ b2,
                        const float* __restrict__ w3,
                        const float* __restrict__ mixw,
                        const float* __restrict__ gb,
                        float* __restrict__ out)
{
    extern __shared__ float smem[];
    float* Zs  = smem + OFF_ZS;
    float* Wt  = smem + OFF_WT;
    float* w2s = smem + OFF_W2;
    float* w1s = smem + OFF_W1;
    float* w3s = smem + OFF_W3;
    float* b1s = smem + OFF_B1;
    float* b2s = smem + OFF_B2;
    float* gts = smem + OFF_G;
    float* scs = smem + OFF_SC;

    const int tid = threadIdx.x;
    const int row0 = blockIdx.x * ROWS;

    // ---- load MLP weights (L2-resident) ----
    #pragma unroll 4
    for (int i = tid; i < 64 * 64; i += THREADS) w2s[i] = w2[i];
    for (int i = tid; i < 512; i += THREADS) { w1s[i] = w1[i]; w3s[i] = w3[i]; }
    if (tid < 64) { b1s[tid] = b1[tid]; b2s[tid] = b2[tid]; }
    if (tid < 8)  gts[tid] = 1.0f / (1.0f + expf(-gb[tid]));

    // ---- mix_w: transpose [i][j][k][d] -> Wt[jd][ik], coalesced global reads ----
    #pragma unroll
    for (int e = 0; e < 16384 / THREADS; ++e) {
        int g = e * THREADS + tid;
        int i = g >> 11, j = (g >> 8) & 7, k = (g >> 4) & 15, d = g & 15;
        Wt[(j * 16 + d) * WT_STRIDE + i * 16 + k] = mixw[g];
    }

    // ---- z tile: coalesced float4 -> padded row-major SMEM ----
    {
        const float4* zg = (const float4*)(z + (size_t)row0 * KDIM);
        #pragma unroll
        for (int e = 0; e < (ROWS * KDIM / 4) / THREADS; ++e) {
            int idx = e * THREADS + tid;      // float4 index
            int r = idx >> 5, c4 = idx & 31;  // 32 float4 per row
            *(float4*)(Zs + r * ZS_STRIDE + c4 * 4) = zg[idx];
        }
    }
    __syncthreads();

    // ---- mixing GEMM: C[128 rows][128 cols], 8x8 microtile, packed f32x2 FMA ----
    const int tx = tid & 15;    // col group: cols tx*8 .. tx*8+7
    const int ty = tid >> 4;    // row group: rows ty*8 .. ty*8+7

    unsigned long long acc[8][4];
    #pragma unroll
    for (int r = 0; r < 8; ++r)
        #pragma unroll
        for (int c = 0; c < 4; ++c) acc[r][c] = 0ull;

    {
        const float* Zrow = Zs + ty * 8 * ZS_STRIDE;
        const float* Wcol = Wt + tx * 8;
        #pragma unroll 4
        for (int jd = 0; jd < KDIM; ++jd) {
            const ulonglong2* wv = (const ulonglong2*)(Wcol + jd * WT_STRIDE);
            ulonglong2 w01 = wv[0];
            ulonglong2 w23 = wv[1];
            #pragma unroll
            for (int r = 0; r < 8; ++r) {
                float av = Zrow[r * ZS_STRIDE + jd];
                unsigned long long ap = pack2(av, av);
                fma2(acc[r][0], ap, w01.x);
                fma2(acc[r][1], ap, w01.y);
                fma2(acc[r][2], ap, w23.x);
                fma2(acc[r][3], ap, w23.y);
            }
        }
    }

    // ---- norms + gating MLP: one thread per row (threads 0..127 = 1 warp/SMSP) ----
    if (tid < ROWS) {
        const float* zr = Zs + tid * ZS_STRIDE;
        float nrm[8];
        #pragma unroll
        for (int j = 0; j < 8; ++j) {
            float s = 0.0f;
            #pragma unroll
            for (int d = 0; d < 16; ++d) { float v = zr[j * 16 + d]; s += v * v; }
            nrm[j] = sqrtf(s) + 1e-8f;
        }
        float h1[64];
        #pragma unroll
        for (int o = 0; o < 64; ++o) {
            float a = b1s[o];
            #pragma unroll
            for (int j = 0; j < 8; ++j) a += nrm[j] * w1s[o * 8 + j];
            h1[o] = gelu_exact(a);
        }
        // layer2 fused with layer3 accumulation (no h2 array)
        float sacc[8];
        #pragma unroll
        for (int j = 0; j < 8; ++j) sacc[j] = 0.0f;
        for (int o = 0; o < 64; ++o) {
            float a = b2s[o];
            #pragma unroll 16
            for (int i = 0; i < 64; ++i) a += h1[i] * w2s[o * 64 + i];
            float h2o = gelu_exact(a);
            #pragma unroll
            for (int j = 0; j < 8; ++j) sacc[j] += h2o * w3s[j * 64 + o];
        }
        #pragma unroll
        for (int j = 0; j < 8; ++j) scs[tid * 8 + j] = softplus_f(sacc[j]);
    }
    __syncthreads();

    // ---- epilogue: out = z*(1+scale[i]) + gate[i]*mixing ----
    {
        const float g = gts[tx >> 1];  // cols tx*8..tx*8+7 all belong to bundle i = tx/2
        #pragma unroll
        for (int r = 0; r < 8; ++r) {
            int lrow = ty * 8 + r;
            float s1 = 1.0f + scs[lrow * 8 + (tx >> 1)];
            const float* zp = Zs + lrow * ZS_STRIDE + tx * 8;
            float4 z0 = *(const float4*)(zp);
            float4 z1 = *(const float4*)(zp + 4);
            float2 m0 = unpack2(acc[r][0]);
            float2 m1 = unpack2(acc[r][1]);
            float2 m2 = unpack2(acc[r][2]);
            float2 m3 = unpack2(acc[r][3]);
            float4 o0 = make_float4(z0.x * s1 + g * m0.x, z0.y * s1 + g * m0.y,
                                    z0.z * s1 + g * m1.x, z0.w * s1 + g * m1.y);
            float4 o1 = make_float4(z1.x * s1 + g * m2.x, z1.y * s1 + g * m2.y,
                                    z1.z * s1 + g * m3.x, z1.w * s1 + g * m3.y);
            float* op = out + (size_t)(row0 + lrow) * KDIM + tx * 8;
            *(float4*)(op)     = o0;
            *(float4*)(op + 4) = o1;
        }
    }
}

extern "C" void kernel_launch(void* const* d_in, const int* in_sizes, int n_in,
                              void* d_out, int out_size)
{
    const float* z    = (const float*)d_in[0];
    const float* w1   = (const float*)d_in[1];
    const float* b1   = (const float*)d_in[2];
    const float* w2   = (const float*)d_in[3];
    const float* b2   = (const float*)d_in[4];
    const float* w3   = (const float*)d_in[5];
    const float* mixw = (const float*)d_in[6];
    const float* gb   = (const float*)d_in[7];
    float* out = (float*)d_out;

    int Btot = in_sizes[0] / 128;          // 524288
    int nblocks = Btot / ROWS;             // 4096

    cudaFuncSetAttribute(soft_equivariant_kernel,
                         cudaFuncAttributeMaxDynamicSharedMemorySize, SMEM_BYTES);
    soft_equivariant_kernel<<<nblocks, THREADS, SMEM_BYTES>>>(
        z, w1, b1, w2, b2, w3, mixw, gb, out);
}

// round 3
// speedup vs baseline: 1.4991x; 1.4991x over previous
#include <cuda_runtime.h>
#include <math.h>

// SoftEquivariantLayer fused kernel v2.
// 512 threads/block, 128 rows/block. GEMM: 8x4 microtile, packed f32x2 FMA,
// vectorized SMEM loads. MLP runs BEFORE the GEMM on threads 0..127 so its
// 64 h1 registers don't overlap the GEMM accumulators' live range.

#define ROWS      128
#define THREADS   512
#define KDIM      128
#define ZS_STRIDE 132
#define WT_STRIDE 132

// shared layout (floats)
#define OFF_ZS     0                          // [128][132]
#define OFF_WT     (OFF_ZS + ROWS*ZS_STRIDE)  // [128][132]  Wt[jd][ik]
#define OFF_W2     (OFF_WT + KDIM*WT_STRIDE)  // [64][64]
#define OFF_W1     (OFF_W2 + 64*64)           // [64][8]
#define OFF_W3     (OFF_W1 + 64*8)            // [8][64]
#define OFF_B1     (OFF_W3 + 8*64)            // [64]
#define OFF_B2     (OFF_B1 + 64)              // [64]
#define OFF_G      (OFF_B2 + 64)              // [8]
#define OFF_SC     (OFF_G + 8)                // [128][8]
#define SMEM_FLOATS (OFF_SC + ROWS*8)
#define SMEM_BYTES  (SMEM_FLOATS * 4)

__device__ __forceinline__ unsigned long long pack2(float lo, float hi) {
    unsigned long long r;
    asm("mov.b64 %0, {%1,%2};" : "=l"(r) : "f"(lo), "f"(hi));
    return r;
}
__device__ __forceinline__ void fma2(unsigned long long& d, unsigned long long a, unsigned long long b) {
    asm("fma.rn.f32x2 %0, %1, %2, %0;" : "+l"(d) : "l"(a), "l"(b));
}
__device__ __forceinline__ float2 unpack2(unsigned long long v) {
    float2 f;
    asm("mov.b64 {%0,%1}, %2;" : "=f"(f.x), "=f"(f.y) : "l"(v));
    return f;
}
__device__ __forceinline__ float gelu_exact(float x) {
    return 0.5f * x * (1.0f + erff(x * 0.7071067811865476f));
}
__device__ __forceinline__ float softplus_f(float x) {
    if (x > 0.0f) return x + log1pf(expf(-x));
    return log1pf(expf(x));
}

__global__ void __launch_bounds__(THREADS, 1)
soft_equivariant_kernel(const float* __restrict__ z,
                        const float* __restrict__ w1,
                        const float* __restrict__ b1,
                        const float* __restrict__ w2,
                        const float* __restrict__ b2,
                        const float* __restrict__ w3,
                        const float* __restrict__ mixw,
                        const float* __restrict__ gb,
                        float* __restrict__ out)
{
    extern __shared__ float smem[];
    float* Zs  = smem + OFF_ZS;
    float* Wt  = smem + OFF_WT;
    float* w2s = smem + OFF_W2;
    float* w1s = smem + OFF_W1;
    float* w3s = smem + OFF_W3;
    float* b1s = smem + OFF_B1;
    float* b2s = smem + OFF_B2;
    float* gts = smem + OFF_G;
    float* scs = smem + OFF_SC;

    const int tid = threadIdx.x;
    const int row0 = blockIdx.x * ROWS;

    // ---- load MLP weights (L2-resident) ----
    #pragma unroll
    for (int e = 0; e < 4096 / THREADS; ++e) {
        int i = e * THREADS + tid;
        w2s[i] = w2[i];
    }
    if (tid < 512) { w1s[tid] = w1[tid]; w3s[tid] = w3[tid]; }
    if (tid < 64) { b1s[tid] = b1[tid]; b2s[tid] = b2[tid]; }
    if (tid < 8)  gts[tid] = 1.0f / (1.0f + expf(-gb[tid]));

    // ---- mix_w: transpose [i][j][k][d] -> Wt[jd][ik] ----
    #pragma unroll
    for (int e = 0; e < 16384 / THREADS; ++e) {
        int g = e * THREADS + tid;
        int i = g >> 11, j = (g >> 8) & 7, k = (g >> 4) & 15, d = g & 15;
        Wt[(j * 16 + d) * WT_STRIDE + i * 16 + k] = mixw[g];
    }

    // ---- z tile: coalesced float4 -> padded row-major SMEM ----
    {
        const float4* zg = (const float4*)(z + (size_t)row0 * KDIM);
        #pragma unroll
        for (int e = 0; e < (ROWS * KDIM / 4) / THREADS; ++e) {
            int idx = e * THREADS + tid;
            int r = idx >> 5, c4 = idx & 31;
            *(float4*)(Zs + r * ZS_STRIDE + c4 * 4) = zg[idx];
        }
    }
    __syncthreads();

    // ---- norms + gating MLP FIRST (threads 0..127 = 1 warp per SMSP) ----
    // h1 lives in registers; its live range ends before GEMM accumulators start.
    if (tid < ROWS) {
        const float* zr = Zs + tid * ZS_STRIDE;
        float nrm[8];
        #pragma unroll
        for (int j = 0; j < 8; ++j) {
            float s = 0.0f;
            #pragma unroll
            for (int d = 0; d < 16; ++d) { float v = zr[j * 16 + d]; s += v * v; }
            nrm[j] = sqrtf(s) + 1e-8f;
        }
        // layer 1 -> h1 (registers), then pack into f32x2 pairs
        unsigned long long hp[32];
        #pragma unroll
        for (int o2 = 0; o2 < 32; ++o2) {
            float a0 = b1s[2 * o2], a1 = b1s[2 * o2 + 1];
            #pragma unroll
            for (int j = 0; j < 8; ++j) {
                a0 += nrm[j] * w1s[(2 * o2) * 8 + j];
                a1 += nrm[j] * w1s[(2 * o2 + 1) * 8 + j];
            }
            hp[o2] = pack2(gelu_exact(a0), gelu_exact(a1));
        }
        // layer 2 (packed fma2, 2 accumulator chains per output) fused with layer 3
        float sacc[8];
        #pragma unroll
        for (int j = 0; j < 8; ++j) sacc[j] = 0.0f;
        const unsigned long long* w2u = (const unsigned long long*)w2s;
        #pragma unroll 2
        for (int o = 0; o < 64; ++o) {
            unsigned long long pa = 0ull, pb = 0ull;
            const unsigned long long* wrow = w2u + o * 32;
            #pragma unroll
            for (int i = 0; i < 32; i += 2) {
                fma2(pa, hp[i],     wrow[i]);
                fma2(pb, hp[i + 1], wrow[i + 1]);
            }
            float2 fa = unpack2(pa), fb = unpack2(pb);
            float h2o = gelu_exact(b2s[o] + (fa.x + fa.y) + (fb.x + fb.y));
            #pragma unroll
            for (int j = 0; j < 8; ++j) sacc[j] += h2o * w3s[j * 64 + o];
        }
        #pragma unroll
        for (int j = 0; j < 8; ++j) scs[tid * 8 + j] = softplus_f(sacc[j]);
    }
    __syncthreads();

    // ---- mixing GEMM: C[128 rows][128 cols], 8 rows x 4 cols per thread ----
    const int tx = tid & 31;    // col group: cols tx*4 .. tx*4+3
    const int ty = tid >> 5;    // row group: rows ty*8 .. ty*8+7

    unsigned long long acc[8][2];
    #pragma unroll
    for (int r = 0; r < 8; ++r) { acc[r][0] = 0ull; acc[r][1] = 0ull; }

    {
        const float* Zr = Zs + (ty * 8) * ZS_STRIDE;
        const float* Wc = Wt + tx * 4;
        #pragma unroll 2
        for (int jd0 = 0; jd0 < KDIM; jd0 += 4) {
            ulonglong2 w0 = *(const ulonglong2*)(Wc + (jd0 + 0) * WT_STRIDE);
            ulonglong2 w1v = *(const ulonglong2*)(Wc + (jd0 + 1) * WT_STRIDE);
            ulonglong2 w2v = *(const ulonglong2*)(Wc + (jd0 + 2) * WT_STRIDE);
            ulonglong2 w3v = *(const ulonglong2*)(Wc + (jd0 + 3) * WT_STRIDE);
            #pragma unroll
            for (int r = 0; r < 8; ++r) {
                float4 a = *(const float4*)(Zr + r * ZS_STRIDE + jd0);
                unsigned long long ax = pack2(a.x, a.x);
                unsigned long long ay = pack2(a.y, a.y);
                unsigned long long az = pack2(a.z, a.z);
                unsigned long long aw = pack2(a.w, a.w);
                fma2(acc[r][0], ax, w0.x);  fma2(acc[r][1], ax, w0.y);
                fma2(acc[r][0], ay, w1v.x); fma2(acc[r][1], ay, w1v.y);
                fma2(acc[r][0], az, w2v.x); fma2(acc[r][1], az, w2v.y);
                fma2(acc[r][0], aw, w3v.x); fma2(acc[r][1], aw, w3v.y);
            }
        }
    }

    // ---- epilogue: out = z*(1+scale[i]) + gate[i]*mixing ----
    {
        const int bundle = tx >> 2;          // 4 cols per thread, 16 cols per bundle
        const float g = gts[bundle];
        #pragma unroll
        for (int r = 0; r < 8; ++r) {
            int lrow = ty * 8 + r;
            float s1 = 1.0f + scs[lrow * 8 + bundle];
            float4 z0 = *(const float4*)(Zs + lrow * ZS_STRIDE + tx * 4);
            float2 m0 = unpack2(acc[r][0]);
            float2 m1 = unpack2(acc[r][1]);
            float4 o0 = make_float4(z0.x * s1 + g * m0.x, z0.y * s1 + g * m0.y,
                                    z0.z * s1 + g * m1.x, z0.w * s1 + g * m1.y);
            *(float4*)(out + (size_t)(row0 + lrow) * KDIM + tx * 4) = o0;
        }
    }
}

extern "C" void kernel_launch(void* const* d_in, const int* in_sizes, int n_in,
                              void* d_out, int out_size)
{
    const float* z    = (const float*)d_in[0];
    const float* w1   = (const float*)d_in[1];
    const float* b1   = (const float*)d_in[2];
    const float* w2   = (const float*)d_in[3];
    const float* b2   = (const float*)d_in[4];
    const float* w3   = (const float*)d_in[5];
    const float* mixw = (const float*)d_in[6];
    const float* gb   = (const float*)d_in[7];
    float* out = (float*)d_out;

    int Btot = in_sizes[0] / 128;          // 524288 rows
    int nblocks = Btot / ROWS;             // 4096

    cudaFuncSetAttribute(soft_equivariant_kernel,
                         cudaFuncAttributeMaxDynamicSharedMemorySize, SMEM_BYTES);
    soft_equivariant_kernel<<<nblocks, THREADS, SMEM_BYTES>>>(
        z, w1, b1, w2, b2, w3, mixw, gb, out);
}

// round 5
// speedup vs baseline: 1.7715x; 1.1817x over previous
#include <cuda_runtime.h>
#include <math.h>
#include <stdint.h>

// SoftEquivariantLayer v4: mixing GEMM on mma.sync tf32 (HMMA, base-target safe),
// k-permuted SMEM layout for vectorized fragment loads, MLP 4-way parallel.
//
// out[b,ik] = z[b,ik]*(1+softplus(MLP(norms))[i]) + sigmoid(gate_bias[i])*mixing[b,ik]
// mixing = Z[128x128] @ Wb^T, Wb[ik][jd] = mix_w[i][j][k][d].

#define ROWS    128
#define THREADS 512
#define ZSTRIDE 144            // floats per row (36 float4), k-permuted layout

// ---- SMEM byte offsets ----
#define A_B     0              // Z tile   [128][144] f32 (73728 B)
#define B_B     73728          // Wb tile  [128][144] f32 (73728 B)
#define W2_B    147456         // 16384 B
#define W1_B    163840         // 2048 B
#define W3_B    165888         // 2048 B
#define B1_B    167936         // 256 B
#define B2_B    168192         // 256 B
#define G_B     168448         // 32 B
#define NRM_B   168480         // [128][8] f32 (4096 B)
#define PART_B  172576         // [4][128][8] f32 (16384 B)
#define SC_B    188960         // [128][8] f32 (4096 B)
#define SMEM_BYTES 193056

__device__ float gWb[128 * ZSTRIDE];   // mix_w transposed + k-permuted

// ---------------- helpers ----------------
static __device__ __forceinline__ unsigned long long pack2(float lo, float hi) {
    unsigned long long r; asm("mov.b64 %0, {%1,%2};" : "=l"(r) : "f"(lo), "f"(hi)); return r;
}
static __device__ __forceinline__ void fma2(unsigned long long& d, unsigned long long a, unsigned long long b) {
    asm("fma.rn.f32x2 %0, %1, %2, %0;" : "+l"(d) : "l"(a), "l"(b));
}
static __device__ __forceinline__ float2 unpack2(unsigned long long v) {
    float2 f; asm("mov.b64 {%0,%1}, %2;" : "=f"(f.x), "=f"(f.y) : "l"(v)); return f;
}
static __device__ __forceinline__ float gelu_exact(float x) {
    return 0.5f * x * (1.0f + erff(x * 0.7071067811865476f));
}
static __device__ __forceinline__ float softplus_f(float x) {
    if (x > 0.0f) return x + log1pf(expf(-x));
    return log1pf(expf(x));
}
// mma.sync m16n8k8 tf32: D += A*B, fragments in f32 bit-patterns (HW truncates to tf32)
static __device__ __forceinline__ void mma8(float4& d, uint32_t a0, uint32_t a1,
                                            uint32_t a2, uint32_t a3,
                                            uint32_t b0, uint32_t b1) {
    asm volatile("mma.sync.aligned.m16n8k8.row.col.f32.tf32.tf32.f32 "
                 "{%0,%1,%2,%3}, {%4,%5,%6,%7}, {%8,%9}, {%0,%1,%2,%3};"
                 : "+f"(d.x), "+f"(d.y), "+f"(d.z), "+f"(d.w)
                 : "r"(a0), "r"(a1), "r"(a2), "r"(a3), "r"(b0), "r"(b1));
}

// ---------------- prep: mix_w -> gWb (transpose + k-permute) ----------------
__global__ void prep_kernel(const float* __restrict__ mixw) {
    int g = blockIdx.x * 256 + threadIdx.x;          // 16384 elems
    int i = g >> 11, j = (g >> 8) & 7, k = (g >> 4) & 15, d = g & 15;
    int n  = i * 16 + k;                              // output col
    int kd = j * 16 + d;                              // K index
    int p  = (kd & 3) * 36 + (kd >> 2);               // permuted col
    gWb[n * ZSTRIDE + p] = mixw[g];
}

// ---------------- main fused kernel ----------------
__global__ void __launch_bounds__(THREADS, 1)
soft_equivariant_kernel(const float* __restrict__ z,
                        const float* __restrict__ w1,
                        const float* __restrict__ b1,
                        const float* __restrict__ w2,
                        const float* __restrict__ b2,
                        const float* __restrict__ w3,
                        const float* __restrict__ gb,
                        float* __restrict__ out)
{
    extern __shared__ char smem[];
    float* Zf  = (float*)(smem + A_B);
    float* Wf  = (float*)(smem + B_B);
    float* w1s = (float*)(smem + W1_B);
    float* w2s = (float*)(smem + W2_B);
    float* w3s = (float*)(smem + W3_B);
    float* b1s = (float*)(smem + B1_B);
    float* b2s = (float*)(smem + B2_B);
    float* gts = (float*)(smem + G_B);
    float* nrs = (float*)(smem + NRM_B);
    float* pts = (float*)(smem + PART_B);
    float* scs = (float*)(smem + SC_B);

    const int tid = threadIdx.x;
    const int wid = tid >> 5;
    const int lid = tid & 31;
    const int row0 = blockIdx.x * ROWS;

    // ---- weights ----
    {
        const float4* s = (const float4*)w2;
        float4* d4 = (float4*)w2s;
        d4[tid] = s[tid]; d4[tid + 512] = s[tid + 512];
        w1s[tid] = w1[tid];
        w3s[tid] = w3[tid];
        if (tid < 64) { b1s[tid] = b1[tid]; b2s[tid] = b2[tid]; }
        if (tid < 8)  gts[tid] = 1.0f / (1.0f + expf(-gb[tid]));
    }

    // ---- B tile: linear copy of pre-permuted gWb (L2-resident) ----
    {
        const float4* s = (const float4*)gWb;
        float4* d4 = (float4*)Wf;
        #pragma unroll
        for (int e = 0; e < 9; ++e) d4[e * THREADS + tid] = s[e * THREADS + tid];
    }

    // ---- A tile: z -> k-permuted layout ----
    {
        const float4* zg = (const float4*)(z + (size_t)row0 * 128);
        #pragma unroll
        for (int e = 0; e < 8; ++e) {
            int idx = e * THREADS + tid;     // float4 index 0..4095
            int row = idx >> 5;
            int w   = idx & 31;              // k0 = 4*w
            float4 v = zg[idx];
            float* dst = Zf + row * ZSTRIDE + w;   // p = c*36 + w
            dst[0]   = v.x;
            dst[36]  = v.y;
            dst[72]  = v.z;
            dst[108] = v.w;
        }
    }
    __syncthreads();

    // ---- norms: 4 threads per row, quad shfl reduce ----
    {
        const int row = tid >> 2, c = tid & 3;
        const float4* zr = (const float4*)(Zf + row * ZSTRIDE + c * 36);
        float part[8];
        #pragma unroll
        for (int j = 0; j < 8; ++j) {
            float4 v = zr[j];
            part[j] = v.x * v.x + v.y * v.y + v.z * v.z + v.w * v.w;
        }
        #pragma unroll
        for (int j = 0; j < 8; ++j) {
            part[j] += __shfl_xor_sync(0xffffffffu, part[j], 1);
            part[j] += __shfl_xor_sync(0xffffffffu, part[j], 2);
        }
        if (c == 0) {
            float4* np = (float4*)(nrs + row * 8);
            np[0] = make_float4(sqrtf(part[0]) + 1e-8f, sqrtf(part[1]) + 1e-8f,
                                sqrtf(part[2]) + 1e-8f, sqrtf(part[3]) + 1e-8f);
            np[1] = make_float4(sqrtf(part[4]) + 1e-8f, sqrtf(part[5]) + 1e-8f,
                                sqrtf(part[6]) + 1e-8f, sqrtf(part[7]) + 1e-8f);
        }
    }
    __syncthreads();

    // ---- gating MLP, 4-way parallel over layer-2 outputs ----
    {
        const int p = tid >> 7;
        const int row = tid & 127;
        float4 na = ((const float4*)(nrs + row * 8))[0];
        float4 nb = ((const float4*)(nrs + row * 8))[1];
        float nrm[8] = {na.x, na.y, na.z, na.w, nb.x, nb.y, nb.z, nb.w};
        unsigned long long hp[32];
        #pragma unroll
        for (int o2 = 0; o2 < 32; ++o2) {
            float a0 = b1s[2 * o2], a1 = b1s[2 * o2 + 1];
            #pragma unroll
            for (int j = 0; j < 8; ++j) {
                a0 += nrm[j] * w1s[(2 * o2) * 8 + j];
                a1 += nrm[j] * w1s[(2 * o2 + 1) * 8 + j];
            }
            hp[o2] = pack2(gelu_exact(a0), gelu_exact(a1));
        }
        float sacc[8];
        #pragma unroll
        for (int j = 0; j < 8; ++j) sacc[j] = 0.0f;
        const unsigned long long* w2u = (const unsigned long long*)w2s;
        for (int oo = 0; oo < 16; ++oo) {
            int o = p * 16 + oo;
            unsigned long long pa = 0ull, pb = 0ull;
            const unsigned long long* wr = w2u + o * 32;
            #pragma unroll
            for (int i = 0; i < 32; i += 2) { fma2(pa, hp[i], wr[i]); fma2(pb, hp[i + 1], wr[i + 1]); }
            float2 fa = unpack2(pa), fb = unpack2(pb);
            float h2o = gelu_exact(b2s[o] + (fa.x + fa.y) + (fb.x + fb.y));
            #pragma unroll
            for (int j = 0; j < 8; ++j) sacc[j] += h2o * w3s[j * 64 + o];
        }
        float4* pp = (float4*)(pts + (p * 128 + row) * 8);
        pp[0] = make_float4(sacc[0], sacc[1], sacc[2], sacc[3]);
        pp[1] = make_float4(sacc[4], sacc[5], sacc[6], sacc[7]);
    }
    __syncthreads();

    // ---- reduce partials -> softplus -> scales ----
    if (tid < ROWS) {
        float s[8] = {0, 0, 0, 0, 0, 0, 0, 0};
        #pragma unroll
        for (int p = 0; p < 4; ++p) {
            float4 a = ((const float4*)(pts + (p * 128 + tid) * 8))[0];
            float4 b = ((const float4*)(pts + (p * 128 + tid) * 8))[1];
            s[0] += a.x; s[1] += a.y; s[2] += a.z; s[3] += a.w;
            s[4] += b.x; s[5] += b.y; s[6] += b.z; s[7] += b.w;
        }
        float4* sp = (float4*)(scs + tid * 8);
        sp[0] = make_float4(softplus_f(s[0]), softplus_f(s[1]), softplus_f(s[2]), softplus_f(s[3]));
        sp[1] = make_float4(softplus_f(s[4]), softplus_f(s[5]), softplus_f(s[6]), softplus_f(s[7]));
    }
    __syncthreads();

    // ---- mixing GEMM: 16 warps, each a 32x32 tile; mma.sync m16n8k8 tf32 ----
    const int mw = wid >> 2;       // row block (32 rows)
    const int nw = wid & 3;        // col block (32 cols)
    const int qt = lid >> 2;       // groupID
    const int qc = lid & 3;        // thread-in-group

    float4 acc[2][4];
    #pragma unroll
    for (int mt = 0; mt < 2; ++mt)
        #pragma unroll
        for (int nt = 0; nt < 4; ++nt) acc[mt][nt] = make_float4(0.f, 0.f, 0.f, 0.f);

    {
        const float4* Z4 = (const float4*)Zf;
        const float4* W4 = (const float4*)Wf;
        #pragma unroll
        for (int ch = 0; ch < 8; ++ch) {       // 16 k per chunk = 2 k-steps
            float4 Af[4];                      // [mt*2+rh]
            #pragma unroll
            for (int mt = 0; mt < 2; ++mt)
                #pragma unroll
                for (int rh = 0; rh < 2; ++rh) {
                    int r = mw * 32 + mt * 16 + rh * 8 + qt;
                    Af[mt * 2 + rh] = Z4[r * 36 + qc * 9 + ch];
                }
            float4 Bf[4];
            #pragma unroll
            for (int nt = 0; nt < 4; ++nt) {
                int n = nw * 32 + nt * 8 + qt;
                Bf[nt] = W4[n * 36 + qc * 9 + ch];
            }
            #pragma unroll
            for (int mt = 0; mt < 2; ++mt) {
                uint32_t a0 = __float_as_uint(Af[2 * mt].x);
                uint32_t a1 = __float_as_uint(Af[2 * mt + 1].x);
                uint32_t a2 = __float_as_uint(Af[2 * mt].y);
                uint32_t a3 = __float_as_uint(Af[2 * mt + 1].y);
                uint32_t c0 = __float_as_uint(Af[2 * mt].z);
                uint32_t c1 = __float_as_uint(Af[2 * mt + 1].z);
                uint32_t c2 = __float_as_uint(Af[2 * mt].w);
                uint32_t c3 = __float_as_uint(Af[2 * mt + 1].w);
                #pragma unroll
                for (int nt = 0; nt < 4; ++nt) {
                    mma8(acc[mt][nt], a0, a1, a2, a3,
                         __float_as_uint(Bf[nt].x), __float_as_uint(Bf[nt].y));
                    mma8(acc[mt][nt], c0, c1, c2, c3,
                         __float_as_uint(Bf[nt].z), __float_as_uint(Bf[nt].w));
                }
            }
        }
    }

    // ---- epilogue: out = z*(1+scale) + gate*mixing ----
    {
        #pragma unroll
        for (int mt = 0; mt < 2; ++mt) {
            #pragma unroll
            for (int nt = 0; nt < 4; ++nt) {
                const int bundle = nw * 2 + (nt >> 1);
                const float g = gts[bundle];
                const int x0 = nw * 32 + nt * 8 + 2 * qc;
                const int p0 = (x0 & 3) * 36 + (x0 >> 2);
                const int p1 = ((x0 + 1) & 3) * 36 + ((x0 + 1) >> 2);
                #pragma unroll
                for (int rh = 0; rh < 2; ++rh) {
                    const int r = mw * 32 + mt * 16 + rh * 8 + qt;
                    const float s1 = 1.0f + scs[r * 8 + bundle];
                    float z0 = Zf[r * ZSTRIDE + p0];
                    float z1 = Zf[r * ZSTRIDE + p1];
                    float m0 = (rh == 0) ? acc[mt][nt].x : acc[mt][nt].z;
                    float m1 = (rh == 0) ? acc[mt][nt].y : acc[mt][nt].w;
                    float2 o = make_float2(z0 * s1 + g * m0, z1 * s1 + g * m1);
                    *(float2*)(out + (size_t)(row0 + r) * 128 + x0) = o;
                }
            }
        }
    }
}

extern "C" void kernel_launch(void* const* d_in, const int* in_sizes, int n_in,
                              void* d_out, int out_size)
{
    const float* z    = (const float*)d_in[0];
    const float* w1   = (const float*)d_in[1];
    const float* b1   = (const float*)d_in[2];
    const float* w2   = (const float*)d_in[3];
    const float* b2   = (const float*)d_in[4];
    const float* w3   = (const float*)d_in[5];
    const float* mixw = (const float*)d_in[6];
    const float* gb   = (const float*)d_in[7];
    float* out = (float*)d_out;

    int Btot = in_sizes[0] / 128;            // 524288 rows
    int nblocks = Btot / ROWS;               // 4096

    prep_kernel<<<64, 256>>>(mixw);

    static bool attr_set = false;
    if (!attr_set) {
        cudaFuncSetAttribute(soft_equivariant_kernel,
                             cudaFuncAttributeMaxDynamicSharedMemorySize, SMEM_BYTES);
        attr_set = true;
    }
    soft_equivariant_kernel<<<nblocks, THREADS, SMEM_BYTES>>>(
        z, w1, b1, w2, b2, w3, gb, out);
}

// round 6
// speedup vs baseline: 2.2923x; 1.2940x over previous
#include <cuda_runtime.h>
#include <math.h>
#include <stdint.h>

// SoftEquivariantLayer v5: warp-specialized — warps 0-7 run the tf32 HMMA mixing
// GEMM, warps 8-15 run norms + gating MLP concurrently (named barriers).
// Fast A&S-7.1.26 erf-GELU (1.5e-7 abs) replaces erff; 2-way MLP split kills
// redundant work. k-permuted SMEM layout as v4 (validated).

#define ROWS    128
#define THREADS 512
#define ZSTRIDE 144            // floats per row (36 float4)

// ---- SMEM byte offsets ----
#define A_B     0              // Z tile   [128][144] f32  (73728)
#define B_B     73728          // Wb tile  [128][144] f32  (73728)
#define H1_B    147456         // u64 [128][33]            (33792)
#define NP_B    181248         // f32 [2][128][8] partials (8192) norms & layer3 share
#define SC_B    189440         // f32 [128][8] scales      (4096)
#define G_B     193536         // f32 [8] gates            (32)
#define W2_B    193600         // 16384
#define W1_B    209984         // 2048
#define W3_B    212032         // 2048
#define B1_B    214080         // 256
#define B2_B    214336         // 256
#define SMEM_BYTES 214624

__device__ float gWb[128 * ZSTRIDE];   // mix_w transposed + k-permuted

// ---------------- helpers ----------------
static __device__ __forceinline__ unsigned long long pack2(float lo, float hi) {
    unsigned long long r; asm("mov.b64 %0, {%1,%2};" : "=l"(r) : "f"(lo), "f"(hi)); return r;
}
static __device__ __forceinline__ void fma2(unsigned long long& d, unsigned long long a, unsigned long long b) {
    asm("fma.rn.f32x2 %0, %1, %2, %0;" : "+l"(d) : "l"(a), "l"(b));
}
static __device__ __forceinline__ float2 unpack2(unsigned long long v) {
    float2 f; asm("mov.b64 {%0,%1}, %2;" : "=f"(f.x), "=f"(f.y) : "l"(v)); return f;
}
// GELU via Abramowitz-Stegun 7.1.26 erf (max abs err 1.5e-7) — no erff.
static __device__ __forceinline__ float gelu_fast(float x) {
    float t = fabsf(x) * 0.7071067811865476f;
    float u = __fdividef(1.0f, fmaf(0.3275911f, t, 1.0f));
    float poly = u * fmaf(u, fmaf(u, fmaf(u, fmaf(u, 1.061405429f, -1.453152027f),
                                          1.421413741f), -0.284496736f), 0.254829592f);
    float e = __expf(-t * t);
    float erfv = fmaf(-poly, e, 1.0f);
    return x * 0.5f * (1.0f + copysignf(erfv, x));
}
static __device__ __forceinline__ float softplus_fast(float x) {
    float e = __expf(-fabsf(x));
    float l = __logf(1.0f + e);
    return x > 0.0f ? x + l : l;
}
// mma.sync m16n8k8 tf32
static __device__ __forceinline__ void mma8(float4& d, uint32_t a0, uint32_t a1,
                                            uint32_t a2, uint32_t a3,
                                            uint32_t b0, uint32_t b1) {
    asm volatile("mma.sync.aligned.m16n8k8.row.col.f32.tf32.tf32.f32 "
                 "{%0,%1,%2,%3}, {%4,%5,%6,%7}, {%8,%9}, {%0,%1,%2,%3};"
                 : "+f"(d.x), "+f"(d.y), "+f"(d.z), "+f"(d.w)
                 : "r"(a0), "r"(a1), "r"(a2), "r"(a3), "r"(b0), "r"(b1));
}
static __device__ __forceinline__ void barrier_mlp() {
    asm volatile("bar.sync 1, 256;" ::: "memory");
}

// ---------------- prep: mix_w -> gWb (transpose + k-permute) ----------------
__global__ void prep_kernel(const float* __restrict__ mixw) {
    int g = blockIdx.x * 256 + threadIdx.x;
    int i = g >> 11, j = (g >> 8) & 7, k = (g >> 4) & 15, d = g & 15;
    int n  = i * 16 + k;
    int kd = j * 16 + d;
    int p  = (kd & 3) * 36 + (kd >> 2);
    gWb[n * ZSTRIDE + p] = mixw[g];
}

// ---------------- main fused kernel ----------------
__global__ void __launch_bounds__(THREADS, 1)
soft_equivariant_kernel(const float* __restrict__ z,
                        const float* __restrict__ w1,
                        const float* __restrict__ b1,
                        const float* __restrict__ w2,
                        const float* __restrict__ b2,
                        const float* __restrict__ w3,
                        const float* __restrict__ gb,
                        float* __restrict__ out)
{
    extern __shared__ char smem[];
    float* Zf  = (float*)(smem + A_B);
    float* Wf  = (float*)(smem + B_B);
    unsigned long long* h1u = (unsigned long long*)(smem + H1_B);
    float* np  = (float*)(smem + NP_B);
    float* scs = (float*)(smem + SC_B);
    float* gts = (float*)(smem + G_B);
    float* w2s = (float*)(smem + W2_B);
    float* w1s = (float*)(smem + W1_B);
    float* w3s = (float*)(smem + W3_B);
    float* b1s = (float*)(smem + B1_B);
    float* b2s = (float*)(smem + B2_B);

    const int tid = threadIdx.x;
    const int wid = tid >> 5;
    const int lid = tid & 31;
    const int row0 = blockIdx.x * ROWS;

    // ---- cooperative loads (all 16 warps) ----
    {
        const float4* s = (const float4*)w2;
        float4* d4 = (float4*)w2s;
        d4[tid] = s[tid]; d4[tid + 512] = s[tid + 512];
        w1s[tid] = w1[tid];
        w3s[tid] = w3[tid];
        if (tid < 64) { b1s[tid] = b1[tid]; b2s[tid] = b2[tid]; }
        if (tid < 8)  gts[tid] = 1.0f / (1.0f + __expf(-gb[tid]));
    }
    {
        const float4* s = (const float4*)gWb;
        float4* d4 = (float4*)Wf;
        #pragma unroll
        for (int e = 0; e < 9; ++e) d4[e * THREADS + tid] = s[e * THREADS + tid];
    }
    {
        const float4* zg = (const float4*)(z + (size_t)row0 * 128);
        #pragma unroll
        for (int e = 0; e < 8; ++e) {
            int idx = e * THREADS + tid;
            int row = idx >> 5;
            int w   = idx & 31;
            float4 v = zg[idx];
            float* dst = Zf + row * ZSTRIDE + w;
            dst[0] = v.x; dst[36] = v.y; dst[72] = v.z; dst[108] = v.w;
        }
    }
    __syncthreads();

    if (wid < 8) {
        // ================= GEMM warps =================
        const int mw = wid & 3;        // rows mw*32..
        const int nh = wid >> 2;       // cols nh*64..
        const int qt = lid >> 2;
        const int qc = lid & 3;

        float4 acc[2][8];
        #pragma unroll
        for (int mt = 0; mt < 2; ++mt)
            #pragma unroll
            for (int nt = 0; nt < 8; ++nt) acc[mt][nt] = make_float4(0.f, 0.f, 0.f, 0.f);

        const float4* Z4 = (const float4*)Zf;
        const float4* W4 = (const float4*)Wf;
        #pragma unroll
        for (int ch = 0; ch < 8; ++ch) {
            float4 Af[4];
            #pragma unroll
            for (int mt = 0; mt < 2; ++mt)
                #pragma unroll
                for (int rh = 0; rh < 2; ++rh) {
                    int r = mw * 32 + mt * 16 + rh * 8 + qt;
                    Af[mt * 2 + rh] = Z4[r * 36 + qc * 9 + ch];
                }
            #pragma unroll
            for (int half = 0; half < 2; ++half) {
                float4 Bf[4];
                #pragma unroll
                for (int t = 0; t < 4; ++t) {
                    int n = nh * 64 + (half * 4 + t) * 8 + qt;
                    Bf[t] = W4[n * 36 + qc * 9 + ch];
                }
                #pragma unroll
                for (int mt = 0; mt < 2; ++mt) {
                    uint32_t a0 = __float_as_uint(Af[2 * mt].x);
                    uint32_t a1 = __float_as_uint(Af[2 * mt + 1].x);
                    uint32_t a2 = __float_as_uint(Af[2 * mt].y);
                    uint32_t a3 = __float_as_uint(Af[2 * mt + 1].y);
                    uint32_t c0 = __float_as_uint(Af[2 * mt].z);
                    uint32_t c1 = __float_as_uint(Af[2 * mt + 1].z);
                    uint32_t c2 = __float_as_uint(Af[2 * mt].w);
                    uint32_t c3 = __float_as_uint(Af[2 * mt + 1].w);
                    #pragma unroll
                    for (int t = 0; t < 4; ++t) {
                        mma8(acc[mt][half * 4 + t], a0, a1, a2, a3,
                             __float_as_uint(Bf[t].x), __float_as_uint(Bf[t].y));
                        mma8(acc[mt][half * 4 + t], c0, c1, c2, c3,
                             __float_as_uint(Bf[t].z), __float_as_uint(Bf[t].w));
                    }
                }
            }
        }
        __syncthreads();     // wait for MLP warps' scales

        // epilogue
        #pragma unroll
        for (int mt = 0; mt < 2; ++mt) {
            #pragma unroll
            for (int nt = 0; nt < 8; ++nt) {
                const int bundle = nh * 4 + (nt >> 1);
                const float g = gts[bundle];
                const int x0 = nh * 64 + nt * 8 + 2 * qc;
                const int p0 = (x0 & 3) * 36 + (x0 >> 2);
                const int p1 = ((x0 + 1) & 3) * 36 + ((x0 + 1) >> 2);
                #pragma unroll
                for (int rh = 0; rh < 2; ++rh) {
                    const int r = mw * 32 + mt * 16 + rh * 8 + qt;
                    const float s1 = 1.0f + scs[r * 8 + bundle];
                    float z0 = Zf[r * ZSTRIDE + p0];
                    float z1 = Zf[r * ZSTRIDE + p1];
                    float m0 = (rh == 0) ? acc[mt][nt].x : acc[mt][nt].z;
                    float m1 = (rh == 0) ? acc[mt][nt].y : acc[mt][nt].w;
                    float2 o = make_float2(z0 * s1 + g * m0, z1 * s1 + g * m1);
                    *(float2*)(out + (size_t)(row0 + r) * 128 + x0) = o;
                }
            }
        }
    } else {
        // ================= MLP warps =================
        const int u = wid - 8;
        const int rgrp = u >> 1;          // 4 groups of 32 rows
        const int h = u & 1;              // half-split
        const int row = rgrp * 32 + lid;
        const float4* Z4 = (const float4*)Zf;

        // ---- norms (half, then exchange) ----
        float pn[8];
        #pragma unroll
        for (int j = 0; j < 8; ++j) pn[j] = 0.0f;
        #pragma unroll
        for (int cc = 0; cc < 2; ++cc) {
            int c = 2 * h + cc;
            #pragma unroll
            for (int j = 0; j < 8; ++j) {
                float4 v = Z4[row * 36 + c * 9 + j];
                pn[j] += v.x * v.x + v.y * v.y + v.z * v.z + v.w * v.w;
            }
        }
        {
            float4* d4 = (float4*)(np + (h * 128 + row) * 8);
            d4[0] = make_float4(pn[0], pn[1], pn[2], pn[3]);
            d4[1] = make_float4(pn[4], pn[5], pn[6], pn[7]);
        }
        barrier_mlp();
        float nrm[8];
        {
            const float4* o4 = (const float4*)(np + ((1 - h) * 128 + row) * 8);
            float4 a = o4[0], b = o4[1];
            nrm[0] = sqrtf(pn[0] + a.x) + 1e-8f; nrm[1] = sqrtf(pn[1] + a.y) + 1e-8f;
            nrm[2] = sqrtf(pn[2] + a.z) + 1e-8f; nrm[3] = sqrtf(pn[3] + a.w) + 1e-8f;
            nrm[4] = sqrtf(pn[4] + b.x) + 1e-8f; nrm[5] = sqrtf(pn[5] + b.y) + 1e-8f;
            nrm[6] = sqrtf(pn[6] + b.z) + 1e-8f; nrm[7] = sqrtf(pn[7] + b.w) + 1e-8f;
        }

        // ---- layer 1 (half: 32 outputs = 16 pairs) ----
        #pragma unroll
        for (int p = 0; p < 16; ++p) {
            int o0 = h * 32 + 2 * p;
            float a0 = b1s[o0], a1 = b1s[o0 + 1];
            #pragma unroll
            for (int j = 0; j < 8; ++j) {
                a0 += nrm[j] * w1s[o0 * 8 + j];
                a1 += nrm[j] * w1s[(o0 + 1) * 8 + j];
            }
            h1u[row * 33 + h * 16 + p] = pack2(gelu_fast(a0), gelu_fast(a1));
        }
        barrier_mlp();

        unsigned long long hp[32];
        #pragma unroll
        for (int p = 0; p < 32; ++p) hp[p] = h1u[row * 33 + p];

        // ---- layer 2 (half: 32 outputs) fused with layer 3 partials ----
        float sacc[8];
        #pragma unroll
        for (int j = 0; j < 8; ++j) sacc[j] = 0.0f;
        #pragma unroll 2
        for (int oo = 0; oo < 32; ++oo) {
            int o = h * 32 + oo;
            unsigned long long pa = 0ull, pb = 0ull;
            const ulonglong2* wr = (const ulonglong2*)(w2s + o * 64);
            #pragma unroll
            for (int ii = 0; ii < 16; ++ii) {
                ulonglong2 q = wr[ii];
                fma2(pa, hp[2 * ii], q.x);
                fma2(pb, hp[2 * ii + 1], q.y);
            }
            float2 fa = unpack2(pa), fb = unpack2(pb);
            float h2o = gelu_fast(b2s[o] + (fa.x + fa.y) + (fb.x + fb.y));
            #pragma unroll
            for (int j = 0; j < 8; ++j) sacc[j] += h2o * w3s[j * 64 + o];
        }
        {
            float4* d4 = (float4*)(np + (h * 128 + row) * 8);
            d4[0] = make_float4(sacc[0], sacc[1], sacc[2], sacc[3]);
            d4[1] = make_float4(sacc[4], sacc[5], sacc[6], sacc[7]);
        }
        barrier_mlp();

        // ---- reduce + softplus (each h-half stores 4 of 8 scales) ----
        {
            const float4* p0 = (const float4*)(np + row * 8) + h;
            const float4* p1 = (const float4*)(np + (128 + row) * 8) + h;
            float4 a = p0[0], b = p1[0];
            float4 r;
            r.x = softplus_fast(a.x + b.x);
            r.y = softplus_fast(a.y + b.y);
            r.z = softplus_fast(a.z + b.z);
            r.w = softplus_fast(a.w + b.w);
            ((float4*)(scs + row * 8))[h] = r;
        }
        __syncthreads();     // release GEMM warps into epilogue
    }
}

extern "C" void kernel_launch(void* const* d_in, const int* in_sizes, int n_in,
                              void* d_out, int out_size)
{
    const float* z    = (const float*)d_in[0];
    const float* w1   = (const float*)d_in[1];
    const float* b1   = (const float*)d_in[2];
    const float* w2   = (const float*)d_in[3];
    const float* b2   = (const float*)d_in[4];
    const float* w3   = (const float*)d_in[5];
    const float* mixw = (const float*)d_in[6];
    const float* gb   = (const float*)d_in[7];
    float* out = (float*)d_out;

    int Btot = in_sizes[0] / 128;            // 524288 rows
    int nblocks = Btot / ROWS;               // 4096

    prep_kernel<<<64, 256>>>(mixw);

    static bool attr_set = false;
    if (!attr_set) {
        cudaFuncSetAttribute(soft_equivariant_kernel,
                             cudaFuncAttributeMaxDynamicSharedMemorySize, SMEM_BYTES);
        attr_set = true;
    }
    soft_equivariant_kernel<<<nblocks, THREADS, SMEM_BYTES>>>(
        z, w1, b1, w2, b2, w3, gb, out);
}